// round 3
// baseline (speedup 1.0000x reference)
#include <cuda_runtime.h>
#include <math.h>
#include <stdint.h>

// Problem constants
#define NT   4096      // total tokens B*S
#define DD   1024      // model dim
#define SS   2048      // sequence length
#define NHQ  16
#define NHKV 4
#define DH   64
#define KVD  (NHKV * DH)   // 256
#define FF   2048      // ffn dim
#define NEXP 8
#define EPS_RMS 1e-5f

// ---------------------------------------------------------------------------
// Scratch (device globals; allocation-free per harness rules). 16B-aligned for
// float4 access (float arrays only guarantee 4B alignment by type).
// ---------------------------------------------------------------------------
__device__ __align__(16) float g_h1  [(size_t)NT * DD];
__device__ __align__(16) float g_q   [(size_t)NT * DD];
__device__ __align__(16) float g_k   [(size_t)NT * KVD];
__device__ __align__(16) float g_v   [(size_t)NT * KVD];
__device__ __align__(16) float g_ctx [(size_t)NT * DD];
__device__ __align__(16) float g_attn[(size_t)NT * DD];
__device__ __align__(16) float g_res2[(size_t)NT * DD];
__device__ __align__(16) float g_flat[(size_t)NT * DD];
__device__ __align__(16) float g_G   [(size_t)NEXP * NT * FF];   // gate / act buffer
__device__ __align__(16) float g_U   [(size_t)NEXP * NT * FF];   // up buffer
__device__ __align__(16) float g_O   [(size_t)NEXP * NT * DD];   // down-proj buffer
__device__ int   g_cnt [NEXP];
__device__ int   g_list[NEXP * NT];
__device__ int   g_tok_e[NT * 2];
__device__ int   g_tok_i[NT * 2];
__device__ float g_tok_w[NT * 2];
__device__ float g_invf[32];

// ---------------------------------------------------------------------------
// Init: zero expert counters, compute rope inv-freq table in double
// ---------------------------------------------------------------------------
__global__ void k_zero_init() {
    int i = threadIdx.x;
    if (i < NEXP) g_cnt[i] = 0;
    if (i < 32) {
        // inv_freq = 10000^(-(2i)/64); log2(10000) = 13.28771237954944939
        double ex = -((double)(2 * i) / 64.0) * 13.28771237954944939;
        g_invf[i] = (float)exp2(ex);
    }
}

// ---------------------------------------------------------------------------
// RMSNorm 1: g_h1 = rmsnorm(hidden, ln1_w)
// ---------------------------------------------------------------------------
__global__ void __launch_bounds__(256) k_rms1(const float* __restrict__ x,
                                              const float* __restrict__ w) {
    int t = blockIdx.x, i = threadIdx.x;
    float4 v = ((const float4*)(x + (size_t)t * DD))[i];
    float ss = v.x * v.x + v.y * v.y + v.z * v.z + v.w * v.w;
    __shared__ float red[8];
    int lane = i & 31, wp = i >> 5;
    #pragma unroll
    for (int o = 16; o; o >>= 1) ss += __shfl_xor_sync(0xffffffffu, ss, o);
    if (!lane) red[wp] = ss;
    __syncthreads();
    if (i == 0) { float s = 0.f; for (int j = 0; j < 8; j++) s += red[j]; red[0] = s; }
    __syncthreads();
    float rs = rsqrtf(red[0] * (1.0f / DD) + EPS_RMS);
    float4 wv = ((const float4*)w)[i];
    ((float4*)(g_h1 + (size_t)t * DD))[i] =
        make_float4(v.x * rs * wv.x, v.y * rs * wv.y, v.z * rs * wv.z, v.w * rs * wv.w);
}

// ---------------------------------------------------------------------------
// Generic tiled SGEMM, 128x128x16, 256 threads, 8x8 per thread.
// Supports expert batching (blockIdx.z), row gather (rowlist), runtime M (counts).
// C[r] = A[gather(r)] @ B   (all row-major). Requires N % 128 == 0, Kd % 16 == 0.
// ---------------------------------------------------------------------------
__global__ void __launch_bounds__(256) k_sgemm(
    const float* __restrict__ A, const float* __restrict__ B, float* __restrict__ C,
    int M, int N, int Kd,
    const int* __restrict__ rowlist, const int* __restrict__ counts,
    size_t strideAe, size_t strideBe, size_t strideCe)
{
    int e  = blockIdx.z;
    int Me = counts ? counts[e] : M;
    int m0 = blockIdx.y * 128;
    if (m0 >= Me) return;
    int n0 = blockIdx.x * 128;
    const float* Ab = A + (size_t)e * strideAe;
    const float* Bb = B + (size_t)e * strideBe;
    float*       Cb = C + (size_t)e * strideCe;

    __shared__ float As[16][128];
    __shared__ float Bs[16][128];

    int tid = threadIdx.x;
    int ty = tid >> 4, tx = tid & 15;

    // A tile load mapping: 512 float4 loads, 2 per thread
    int ac4 = tid & 3;
    int ar0 = tid >> 2;        // 0..63
    int ar1 = 64 + ar0;        // 64..127
    int r0 = m0 + ar0; if (r0 > Me - 1) r0 = Me - 1;
    int r1 = m0 + ar1; if (r1 > Me - 1) r1 = Me - 1;
    const int* lst = rowlist ? (rowlist + e * NT) : (const int*)0;
    size_t gr0 = lst ? (size_t)lst[r0] : (size_t)r0;
    size_t gr1 = lst ? (size_t)lst[r1] : (size_t)r1;
    const float* a0p = Ab + gr0 * (size_t)Kd;
    const float* a1p = Ab + gr1 * (size_t)Kd;

    // B tile load mapping
    int brow = tid >> 5;       // 0..7
    int bc4  = tid & 31;

    float acc[8][8];
    #pragma unroll
    for (int i = 0; i < 8; i++)
        #pragma unroll
        for (int j = 0; j < 8; j++) acc[i][j] = 0.f;

    for (int kt = 0; kt < Kd; kt += 16) {
        float4 va0 = *(const float4*)(a0p + kt + ac4 * 4);
        float4 va1 = *(const float4*)(a1p + kt + ac4 * 4);
        float4 vb0 = *(const float4*)(Bb + (size_t)(kt + brow)     * N + n0 + bc4 * 4);
        float4 vb1 = *(const float4*)(Bb + (size_t)(kt + brow + 8) * N + n0 + bc4 * 4);
        As[ac4 * 4 + 0][ar0] = va0.x; As[ac4 * 4 + 1][ar0] = va0.y;
        As[ac4 * 4 + 2][ar0] = va0.z; As[ac4 * 4 + 3][ar0] = va0.w;
        As[ac4 * 4 + 0][ar1] = va1.x; As[ac4 * 4 + 1][ar1] = va1.y;
        As[ac4 * 4 + 2][ar1] = va1.z; As[ac4 * 4 + 3][ar1] = va1.w;
        *(float4*)&Bs[brow][bc4 * 4]     = vb0;
        *(float4*)&Bs[brow + 8][bc4 * 4] = vb1;
        __syncthreads();
        #pragma unroll
        for (int kk = 0; kk < 16; kk++) {
            float a[8], b[8];
            *(float4*)&a[0] = *(const float4*)&As[kk][ty * 8];
            *(float4*)&a[4] = *(const float4*)&As[kk][ty * 8 + 4];
            *(float4*)&b[0] = *(const float4*)&Bs[kk][tx * 8];
            *(float4*)&b[4] = *(const float4*)&Bs[kk][tx * 8 + 4];
            #pragma unroll
            for (int i = 0; i < 8; i++)
                #pragma unroll
                for (int j = 0; j < 8; j++)
                    acc[i][j] += a[i] * b[j];
        }
        __syncthreads();
    }
    #pragma unroll
    for (int i = 0; i < 8; i++) {
        int r = m0 + ty * 8 + i;
        if (r < Me) {
            float* cp = Cb + (size_t)r * N + n0 + tx * 8;
            *(float4*)cp       = make_float4(acc[i][0], acc[i][1], acc[i][2], acc[i][3]);
            *(float4*)(cp + 4) = make_float4(acc[i][4], acc[i][5], acc[i][6], acc[i][7]);
        }
    }
}

// ---------------------------------------------------------------------------
// RoPE (in place on g_q / g_k)
// ---------------------------------------------------------------------------
__global__ void __launch_bounds__(512) k_rope_q() {
    int t = blockIdx.x;
    int h = threadIdx.x >> 5, i = threadIdx.x & 31;
    int pos = t & (SS - 1);
    float ang = (float)pos * g_invf[i];
    float s, c;
    sincosf(ang, &s, &c);
    size_t base = (size_t)t * DD + h * DH + i;
    float x1 = g_q[base], x2 = g_q[base + 32];
    g_q[base]      = x1 * c - x2 * s;
    g_q[base + 32] = x2 * c + x1 * s;
}

__global__ void __launch_bounds__(128) k_rope_k() {
    int t = blockIdx.x;
    int h = threadIdx.x >> 5, i = threadIdx.x & 31;
    int pos = t & (SS - 1);
    float ang = (float)pos * g_invf[i];
    float s, c;
    sincosf(ang, &s, &c);
    size_t base = (size_t)t * KVD + h * DH + i;
    float x1 = g_k[base], x2 = g_k[base + 32];
    g_k[base]      = x1 * c - x2 * s;
    g_k[base + 32] = x2 * c + x1 * s;
}

// ---------------------------------------------------------------------------
// Causal GQA flash attention. grid (S/128, B*H), 128 threads, 1 q-row/thread.
// dyn smem: K tile 64x64, V tile 64x64, score buf 128x65 (padded)
// ---------------------------------------------------------------------------
__global__ void __launch_bounds__(128) k_attn() {
    int qt = blockIdx.x;
    int bh = blockIdx.y;
    int b = bh >> 4, h = bh & 15, hk = h >> 2;
    int tid = threadIdx.x;
    extern __shared__ float sm[];
    float* Ks = sm;              // 4096
    float* Vs = sm + 4096;       // 4096
    float* Sr = sm + 8192;       // 128*65

    int qi = qt * 128 + tid;
    int t  = b * SS + qi;
    float qreg[64];
    {
        const float4* qp = (const float4*)(g_q + (size_t)t * DD + h * DH);
        #pragma unroll
        for (int u = 0; u < 16; u++) {
            float4 x = qp[u];
            qreg[u * 4 + 0] = x.x * 0.125f; qreg[u * 4 + 1] = x.y * 0.125f;
            qreg[u * 4 + 2] = x.z * 0.125f; qreg[u * 4 + 3] = x.w * 0.125f;
        }
    }
    float acc[64];
    #pragma unroll
    for (int d = 0; d < 64; d++) acc[d] = 0.f;
    float m = -3e38f, l = 0.f;

    int jmax = 2 * qt + 1;
    for (int jt = 0; jt <= jmax; jt++) {
        int kb = b * SS + jt * 64;
        #pragma unroll
        for (int u = 0; u < 8; u++) {
            int lin = u * 128 + tid;
            int row = lin >> 4, c4 = lin & 15;
            *(float4*)(Ks + row * 64 + c4 * 4) =
                *(const float4*)(g_k + (size_t)(kb + row) * KVD + hk * DH + c4 * 4);
            *(float4*)(Vs + row * 64 + c4 * 4) =
                *(const float4*)(g_v + (size_t)(kb + row) * KVD + hk * DH + c4 * 4);
        }
        __syncthreads();
        int lim = qi - jt * 64;
        if (lim >= 0) {
            int cmax = lim < 63 ? lim : 63;
            float smax = -3e38f;
            for (int c = 0; c <= cmax; c++) {
                const float4* kr = (const float4*)(Ks + c * 64);
                float s = 0.f;
                #pragma unroll
                for (int d4 = 0; d4 < 16; d4++) {
                    float4 kv = kr[d4];
                    s += qreg[d4 * 4 + 0] * kv.x; s += qreg[d4 * 4 + 1] * kv.y;
                    s += qreg[d4 * 4 + 2] * kv.z; s += qreg[d4 * 4 + 3] * kv.w;
                }
                Sr[tid * 65 + c] = s;
                smax = fmaxf(smax, s);
            }
            float mnew = fmaxf(m, smax);
            float corr = __expf(m - mnew);
            l *= corr;
            #pragma unroll
            for (int d = 0; d < 64; d++) acc[d] *= corr;
            for (int c = 0; c <= cmax; c++) {
                float p = __expf(Sr[tid * 65 + c] - mnew);
                l += p;
                const float4* vr = (const float4*)(Vs + c * 64);
                #pragma unroll
                for (int d4 = 0; d4 < 16; d4++) {
                    float4 vv = vr[d4];
                    acc[d4 * 4 + 0] += p * vv.x; acc[d4 * 4 + 1] += p * vv.y;
                    acc[d4 * 4 + 2] += p * vv.z; acc[d4 * 4 + 3] += p * vv.w;
                }
            }
            m = mnew;
        }
        __syncthreads();
    }
    float inv = 1.0f / l;
    float4* op = (float4*)(g_ctx + (size_t)t * DD + h * DH);
    #pragma unroll
    for (int u = 0; u < 16; u++)
        op[u] = make_float4(acc[u * 4] * inv, acc[u * 4 + 1] * inv,
                            acc[u * 4 + 2] * inv, acc[u * 4 + 3] * inv);
}

// ---------------------------------------------------------------------------
// residual add + clip + RMSNorm2 -> g_res2 (clipped h), g_flat (normed)
// ---------------------------------------------------------------------------
__global__ void __launch_bounds__(256) k_post(const float* __restrict__ hidden,
                                              const float* __restrict__ w2) {
    int t = blockIdx.x, i = threadIdx.x;
    float4 hv = ((const float4*)(hidden + (size_t)t * DD))[i];
    float4 av = ((const float4*)(g_attn + (size_t)t * DD))[i];
    float4 s;
    s.x = fminf(fmaxf(hv.x + av.x, -100.f), 100.f);
    s.y = fminf(fmaxf(hv.y + av.y, -100.f), 100.f);
    s.z = fminf(fmaxf(hv.z + av.z, -100.f), 100.f);
    s.w = fminf(fmaxf(hv.w + av.w, -100.f), 100.f);
    ((float4*)(g_res2 + (size_t)t * DD))[i] = s;
    float ss = s.x * s.x + s.y * s.y + s.z * s.z + s.w * s.w;
    __shared__ float red[8];
    int lane = i & 31, wp = i >> 5;
    #pragma unroll
    for (int o = 16; o; o >>= 1) ss += __shfl_xor_sync(0xffffffffu, ss, o);
    if (!lane) red[wp] = ss;
    __syncthreads();
    if (i == 0) { float z = 0.f; for (int j = 0; j < 8; j++) z += red[j]; red[0] = z; }
    __syncthreads();
    float rs = rsqrtf(red[0] * (1.0f / DD) + EPS_RMS);
    float4 wv = ((const float4*)w2)[i];
    ((float4*)(g_flat + (size_t)t * DD))[i] =
        make_float4(s.x * rs * wv.x, s.y * rs * wv.y, s.z * rs * wv.z, s.w * rs * wv.w);
}

// ---------------------------------------------------------------------------
// Router: logits -> top2 -> normalized weights -> expert token lists
// ---------------------------------------------------------------------------
__global__ void __launch_bounds__(256) k_router(const float* __restrict__ Wr) {
    int t = blockIdx.x;
    int lane = threadIdx.x & 31, w = threadIdx.x >> 5;   // 8 warps = 8 experts
    const float* fr = g_flat + (size_t)t * DD;
    float s = 0.f;
    for (int d = lane; d < DD; d += 32) s += fr[d] * Wr[d * NEXP + w];
    #pragma unroll
    for (int o = 16; o; o >>= 1) s += __shfl_xor_sync(0xffffffffu, s, o);
    __shared__ float lg[NEXP];
    if (!lane) lg[w] = s;
    __syncthreads();
    if (threadIdx.x == 0) {
        float l0 = -3e38f; int i0 = 0;
        #pragma unroll
        for (int e2 = 0; e2 < NEXP; e2++) if (lg[e2] > l0) { l0 = lg[e2]; i0 = e2; }
        float l1 = -3e38f; int i1 = 0;
        #pragma unroll
        for (int e2 = 0; e2 < NEXP; e2++)
            if (e2 != i0 && lg[e2] > l1) { l1 = lg[e2]; i1 = e2; }
        float p1 = __expf(l1 - l0);
        float w0 = 1.0f / (1.0f + p1), w1 = p1 / (1.0f + p1);
        int pos0 = atomicAdd(&g_cnt[i0], 1);
        g_list[i0 * NT + pos0] = t;
        g_tok_e[t * 2] = i0; g_tok_i[t * 2] = pos0; g_tok_w[t * 2] = w0;
        int pos1 = atomicAdd(&g_cnt[i1], 1);
        g_list[i1 * NT + pos1] = t;
        g_tok_e[t * 2 + 1] = i1; g_tok_i[t * 2 + 1] = pos1; g_tok_w[t * 2 + 1] = w1;
    }
}

// ---------------------------------------------------------------------------
// SiLU(g)*u, in place into g_G
// ---------------------------------------------------------------------------
__global__ void __launch_bounds__(256) k_act() {
    int e = blockIdx.y, r = blockIdx.x;
    if (r >= g_cnt[e]) return;
    size_t base4 = (((size_t)e * NT + r) * FF) >> 2;
    float4* G4 = (float4*)g_G;
    const float4* U4 = (const float4*)g_U;
    for (int f = threadIdx.x; f < FF / 4; f += 256) {
        float4 g = G4[base4 + f], u = U4[base4 + f];
        g.x = g.x / (1.f + __expf(-g.x)) * u.x;
        g.y = g.y / (1.f + __expf(-g.y)) * u.y;
        g.z = g.z / (1.f + __expf(-g.z)) * u.z;
        g.w = g.w / (1.f + __expf(-g.w)) * u.w;
        G4[base4 + f] = g;
    }
}

// ---------------------------------------------------------------------------
// Final combine: out = clip(res2 + w0*O[e0,i0] + w1*O[e1,i1])
// ---------------------------------------------------------------------------
__global__ void __launch_bounds__(256) k_combine(float* __restrict__ out) {
    int t = blockIdx.x, i = threadIdx.x;
    int e0 = g_tok_e[t * 2],     i0 = g_tok_i[t * 2];     float w0 = g_tok_w[t * 2];
    int e1 = g_tok_e[t * 2 + 1], i1 = g_tok_i[t * 2 + 1]; float w1 = g_tok_w[t * 2 + 1];
    const float4* o0 = (const float4*)(g_O + ((size_t)e0 * NT + i0) * DD);
    const float4* o1 = (const float4*)(g_O + ((size_t)e1 * NT + i1) * DD);
    const float4* rr = (const float4*)(g_res2 + (size_t)t * DD);
    float4 a = rr[i], x = o0[i], y = o1[i], o;
    o.x = fminf(fmaxf(a.x + w0 * x.x + w1 * y.x, -100.f), 100.f);
    o.y = fminf(fmaxf(a.y + w0 * x.y + w1 * y.y, -100.f), 100.f);
    o.z = fminf(fmaxf(a.z + w0 * x.z + w1 * y.z, -100.f), 100.f);
    o.w = fminf(fmaxf(a.w + w0 * x.w + w1 * y.w, -100.f), 100.f);
    ((float4*)(out + (size_t)t * DD))[i] = o;
}

// ---------------------------------------------------------------------------
// Host launcher
// ---------------------------------------------------------------------------
extern "C" void kernel_launch(void* const* d_in, const int* in_sizes, int n_in,
                              void* d_out, int out_size) {
    const float* hidden = (const float*)d_in[0];
    const float* ln1    = (const float*)d_in[1];
    const float* ln2    = (const float*)d_in[2];
    const float* Wq     = (const float*)d_in[3];
    const float* Wk     = (const float*)d_in[4];
    const float* Wv     = (const float*)d_in[5];
    const float* Wo     = (const float*)d_in[6];
    const float* Wr     = (const float*)d_in[7];
    const float* Wg     = (const float*)d_in[8];
    const float* Wu     = (const float*)d_in[9];
    const float* Wd     = (const float*)d_in[10];
    float* out = (float*)d_out;
    (void)in_sizes; (void)n_in; (void)out_size;

    float *p_h1, *p_q, *p_k, *p_v, *p_ctx, *p_attn, *p_flat, *p_G, *p_U, *p_O;
    int *p_lst, *p_cnt;
    cudaGetSymbolAddress((void**)&p_h1,  g_h1);
    cudaGetSymbolAddress((void**)&p_q,   g_q);
    cudaGetSymbolAddress((void**)&p_k,   g_k);
    cudaGetSymbolAddress((void**)&p_v,   g_v);
    cudaGetSymbolAddress((void**)&p_ctx, g_ctx);
    cudaGetSymbolAddress((void**)&p_attn,g_attn);
    cudaGetSymbolAddress((void**)&p_flat,g_flat);
    cudaGetSymbolAddress((void**)&p_G,   g_G);
    cudaGetSymbolAddress((void**)&p_U,   g_U);
    cudaGetSymbolAddress((void**)&p_O,   g_O);
    cudaGetSymbolAddress((void**)&p_lst, g_list);
    cudaGetSymbolAddress((void**)&p_cnt, g_cnt);

    const int ATTN_SMEM = (4096 + 4096 + 128 * 65) * 4;   // 66048 B
    static int s_attr_done = 0;
    if (!s_attr_done) {
        cudaFuncSetAttribute(k_attn, cudaFuncAttributeMaxDynamicSharedMemorySize, ATTN_SMEM);
        s_attr_done = 1;
    }

    k_zero_init<<<1, 32>>>();
    k_rms1<<<NT, 256>>>(hidden, ln1);

    // QKV projections. NOTE: Wk/Wv have N = HKV*HD = 256 (bug fixed: was 512)
    k_sgemm<<<dim3(8, 32, 1), 256>>>(p_h1, Wq, p_q, NT, 1024, 1024, 0, 0, 0, 0, 0);
    k_sgemm<<<dim3(2, 32, 1), 256>>>(p_h1, Wk, p_k, NT,  KVD, 1024, 0, 0, 0, 0, 0);
    k_sgemm<<<dim3(2, 32, 1), 256>>>(p_h1, Wv, p_v, NT,  KVD, 1024, 0, 0, 0, 0, 0);

    k_rope_q<<<NT, 512>>>();
    k_rope_k<<<NT, 128>>>();

    k_attn<<<dim3(16, 32), 128, ATTN_SMEM>>>();

    k_sgemm<<<dim3(8, 32, 1), 256>>>(p_ctx, Wo, p_attn, NT, 1024, 1024, 0, 0, 0, 0, 0);

    k_post<<<NT, 256>>>(hidden, ln2);
    k_router<<<NT, 256>>>(Wr);

    // Expert FFN: gather-GEMM G and U, activation, then down-proj
    k_sgemm<<<dim3(16, 32, NEXP), 256>>>(p_flat, Wg, p_G, 0, FF, DD, p_lst, p_cnt,
                                         0, (size_t)DD * FF, (size_t)NT * FF);
    k_sgemm<<<dim3(16, 32, NEXP), 256>>>(p_flat, Wu, p_U, 0, FF, DD, p_lst, p_cnt,
                                         0, (size_t)DD * FF, (size_t)NT * FF);
    k_act<<<dim3(NT, NEXP), 256>>>();
    k_sgemm<<<dim3(8, 32, NEXP), 256>>>(p_G, Wd, p_O, 0, DD, FF, 0, p_cnt,
                                        (size_t)NT * FF, (size_t)FF * DD, (size_t)NT * DD);

    k_combine<<<NT, 256>>>(out);
}

// round 4
// speedup vs baseline: 1.1331x; 1.1331x over previous
#include <cuda_runtime.h>
#include <math.h>
#include <stdint.h>

// Problem constants
#define NT   4096
#define DD   1024
#define SS   2048
#define NHQ  16
#define NHKV 4
#define DH   64
#define KVD  (NHKV * DH)   // 256
#define FF   2048
#define NEXP 8
#define EPS_RMS 1e-5f

#define BM 256
#define BN 128
#define BK 16

typedef unsigned long long ull;

// packed fp32x2 helpers (Blackwell fma.rn.f32x2 — 2 MACs per issue on fma pipe)
__device__ __forceinline__ ull pk2(float x, float y) {
    ull r; asm("mov.b64 %0, {%1, %2};" : "=l"(r) : "f"(x), "f"(y)); return r;
}
__device__ __forceinline__ void fma2(ull& c, ull a, ull b) {
    asm("fma.rn.f32x2 %0, %1, %2, %0;" : "+l"(c) : "l"(a), "l"(b));
}
__device__ __forceinline__ float2 up2(ull v) {
    float2 r; asm("mov.b64 {%0, %1}, %2;" : "=f"(r.x), "=f"(r.y) : "l"(v)); return r;
}

// ---------------------------------------------------------------------------
// Scratch (device globals; allocation-free). 16B-aligned for float4 access.
// ---------------------------------------------------------------------------
__device__ __align__(16) float g_h1  [(size_t)NT * DD];
__device__ __align__(16) float g_q   [(size_t)NT * DD];
__device__ __align__(16) float g_k   [(size_t)NT * KVD];
__device__ __align__(16) float g_v   [(size_t)NT * KVD];
__device__ __align__(16) float g_ctx [(size_t)NT * DD];
__device__ __align__(16) float g_attn[(size_t)NT * DD];
__device__ __align__(16) float g_res2[(size_t)NT * DD];
__device__ __align__(16) float g_flat[(size_t)NT * DD];
__device__ __align__(16) float g_G   [(size_t)NEXP * NT * FF];
__device__ __align__(16) float g_U   [(size_t)NEXP * NT * FF];
__device__ __align__(16) float g_O   [(size_t)NEXP * NT * DD];
__device__ int   g_cnt [NEXP];
__device__ int   g_list[NEXP * NT];
__device__ int   g_tok_e[NT * 2];
__device__ int   g_tok_i[NT * 2];
__device__ float g_tok_w[NT * 2];
__device__ float g_invf[32];

// ---------------------------------------------------------------------------
__global__ void k_zero_init() {
    int i = threadIdx.x;
    if (i < NEXP) g_cnt[i] = 0;
    if (i < 32) {
        double ex = -((double)(2 * i) / 64.0) * 13.28771237954944939; // log2(1e4)
        g_invf[i] = (float)exp2(ex);
    }
}

// ---------------------------------------------------------------------------
// RMSNorm 1
// ---------------------------------------------------------------------------
__global__ void __launch_bounds__(256) k_rms1(const float* __restrict__ x,
                                              const float* __restrict__ w) {
    int t = blockIdx.x, i = threadIdx.x;
    float4 v = ((const float4*)(x + (size_t)t * DD))[i];
    float ss = v.x * v.x + v.y * v.y + v.z * v.z + v.w * v.w;
    __shared__ float red[8];
    int lane = i & 31, wp = i >> 5;
    #pragma unroll
    for (int o = 16; o; o >>= 1) ss += __shfl_xor_sync(0xffffffffu, ss, o);
    if (!lane) red[wp] = ss;
    __syncthreads();
    if (i == 0) { float s = 0.f; for (int j = 0; j < 8; j++) s += red[j]; red[0] = s; }
    __syncthreads();
    float rs = rsqrtf(red[0] * (1.0f / DD) + EPS_RMS);
    float4 wv = ((const float4*)w)[i];
    ((float4*)(g_h1 + (size_t)t * DD))[i] =
        make_float4(v.x * rs * wv.x, v.y * rs * wv.y, v.z * rs * wv.z, v.w * rs * wv.w);
}

// ---------------------------------------------------------------------------
// SGEMM core: 256x128x16 tile, 256 threads, 16Mx8N per thread, packed FFMA2.
// Double-buffered smem + register prefetch. A rows via 4 precomputed pointers.
// ---------------------------------------------------------------------------
__device__ __forceinline__ void sgemm_core(
    const float* a0, const float* a1, const float* a2r, const float* a3,
    const float* __restrict__ B, int ldb, int bcol,
    float* __restrict__ C, int ldc, int ccol,
    int Kd, int Me, int m0)
{
    __shared__ float As[2][BK][BM];   // M-contiguous per kk
    __shared__ float Bs[2][BK][BN];

    int tid = threadIdx.x;
    int ar = tid >> 2, ac4 = tid & 3;      // A loader: 4 rows (ar+64q), k-quad ac4
    int brow = tid >> 5, bc4 = tid & 31;   // B loader
    int tr = tid >> 4, tx = tid & 15;      // compute: rows tr*16..+15, cols tx*8..+7

    const float* ap[4] = {a0, a1, a2r, a3};

    ull acc[8][8];
    #pragma unroll
    for (int i = 0; i < 8; i++)
        #pragma unroll
        for (int j = 0; j < 8; j++) acc[i][j] = 0ull;

    int nk = Kd / BK;
    float4 va[4], vb[2];

    // prologue: tile 0 -> regs -> smem buf 0
    #pragma unroll
    for (int q = 0; q < 4; q++) va[q] = *(const float4*)(ap[q] + ac4 * 4);
    vb[0] = *(const float4*)(B + (size_t)brow * ldb + bcol + bc4 * 4);
    vb[1] = *(const float4*)(B + (size_t)(brow + 8) * ldb + bcol + bc4 * 4);
    #pragma unroll
    for (int q = 0; q < 4; q++) {
        As[0][ac4 * 4 + 0][ar + 64 * q] = va[q].x;
        As[0][ac4 * 4 + 1][ar + 64 * q] = va[q].y;
        As[0][ac4 * 4 + 2][ar + 64 * q] = va[q].z;
        As[0][ac4 * 4 + 3][ar + 64 * q] = va[q].w;
    }
    *(float4*)&Bs[0][brow][bc4 * 4]     = vb[0];
    *(float4*)&Bs[0][brow + 8][bc4 * 4] = vb[1];
    __syncthreads();

    for (int kt = 0; kt < nk; kt++) {
        // prefetch next tile into regs
        if (kt + 1 < nk) {
            int kn = (kt + 1) * BK;
            #pragma unroll
            for (int q = 0; q < 4; q++) va[q] = *(const float4*)(ap[q] + kn + ac4 * 4);
            vb[0] = *(const float4*)(B + (size_t)(kn + brow) * ldb + bcol + bc4 * 4);
            vb[1] = *(const float4*)(B + (size_t)(kn + brow + 8) * ldb + bcol + bc4 * 4);
        }
        int st = kt & 1;
        #pragma unroll
        for (int kk = 0; kk < BK; kk++) {
            float2 af[8];
            *(float4*)&af[0] = *(const float4*)&As[st][kk][tr * 16];
            *(float4*)&af[2] = *(const float4*)&As[st][kk][tr * 16 + 4];
            *(float4*)&af[4] = *(const float4*)&As[st][kk][tr * 16 + 8];
            *(float4*)&af[6] = *(const float4*)&As[st][kk][tr * 16 + 12];
            float4 b0 = *(const float4*)&Bs[st][kk][tx * 8];
            float4 b1 = *(const float4*)&Bs[st][kk][tx * 8 + 4];
            ull bd[8];
            bd[0] = pk2(b0.x, b0.x); bd[1] = pk2(b0.y, b0.y);
            bd[2] = pk2(b0.z, b0.z); bd[3] = pk2(b0.w, b0.w);
            bd[4] = pk2(b1.x, b1.x); bd[5] = pk2(b1.y, b1.y);
            bd[6] = pk2(b1.z, b1.z); bd[7] = pk2(b1.w, b1.w);
            #pragma unroll
            for (int i = 0; i < 8; i++) {
                ull av = *(ull*)&af[i];
                #pragma unroll
                for (int j = 0; j < 8; j++) fma2(acc[i][j], av, bd[j]);
            }
        }
        if (kt + 1 < nk) {
            int s2 = (kt + 1) & 1;
            #pragma unroll
            for (int q = 0; q < 4; q++) {
                As[s2][ac4 * 4 + 0][ar + 64 * q] = va[q].x;
                As[s2][ac4 * 4 + 1][ar + 64 * q] = va[q].y;
                As[s2][ac4 * 4 + 2][ar + 64 * q] = va[q].z;
                As[s2][ac4 * 4 + 3][ar + 64 * q] = va[q].w;
            }
            *(float4*)&Bs[s2][brow][bc4 * 4]     = vb[0];
            *(float4*)&Bs[s2][brow + 8][bc4 * 4] = vb[1];
        }
        __syncthreads();
    }

    // epilogue: acc[i][j] holds rows (tr*16+2i, +2i+1), col tx*8+j
    #pragma unroll
    for (int i = 0; i < 8; i++) {
        float c0[8], c1[8];
        #pragma unroll
        for (int j = 0; j < 8; j++) { float2 u = up2(acc[i][j]); c0[j] = u.x; c1[j] = u.y; }
        int r0 = m0 + tr * 16 + 2 * i;
        if (r0 < Me) {
            float* p = C + (size_t)r0 * ldc + ccol + tx * 8;
            *(float4*)p       = make_float4(c0[0], c0[1], c0[2], c0[3]);
            *(float4*)(p + 4) = make_float4(c0[4], c0[5], c0[6], c0[7]);
        }
        if (r0 + 1 < Me) {
            float* p = C + (size_t)(r0 + 1) * ldc + ccol + tx * 8;
            *(float4*)p       = make_float4(c1[0], c1[1], c1[2], c1[3]);
            *(float4*)(p + 4) = make_float4(c1[4], c1[5], c1[6], c1[7]);
        }
    }
}

// General SGEMM (expert batch + gather + runtime M)
__global__ void __launch_bounds__(256, 1) k_sgemm(
    const float* __restrict__ A, const float* __restrict__ B, float* __restrict__ C,
    int M, int N, int Kd,
    const int* __restrict__ rowlist, const int* __restrict__ counts,
    size_t strideAe, size_t strideBe, size_t strideCe)
{
    int e  = blockIdx.z;
    int Me = counts ? counts[e] : M;
    int m0 = blockIdx.y * BM;
    if (m0 >= Me) return;
    int n0 = blockIdx.x * BN;
    const float* Ab = A + (size_t)e * strideAe;
    const float* Bb = B + (size_t)e * strideBe;
    float*       Cb = C + (size_t)e * strideCe;

    int ar = threadIdx.x >> 2;
    const int* lst = rowlist ? (rowlist + e * NT) : (const int*)0;
    const float* ap[4];
    #pragma unroll
    for (int q = 0; q < 4; q++) {
        int r = m0 + ar + 64 * q; if (r > Me - 1) r = Me - 1;
        size_t gr = lst ? (size_t)lst[r] : (size_t)r;
        ap[q] = Ab + gr * (size_t)Kd;
    }
    sgemm_core(ap[0], ap[1], ap[2], ap[3], Bb, N, n0, Cb, N, n0, Kd, Me, m0);
}

// Fused QKV projection: blockIdx.x picks Wq/Wk/Wv column range
__global__ void __launch_bounds__(256, 1) k_sgemm_qkv(
    const float* __restrict__ h1,
    const float* __restrict__ Wq, const float* __restrict__ Wk,
    const float* __restrict__ Wv)
{
    int bx = blockIdx.x;
    int m0 = blockIdx.y * BM;
    const float* B; float* C; int ldb, bcol;
    if (bx < 8)       { B = Wq; C = g_q; ldb = 1024; bcol = bx * 128; }
    else if (bx < 10) { B = Wk; C = g_k; ldb = KVD;  bcol = (bx - 8) * 128; }
    else              { B = Wv; C = g_v; ldb = KVD;  bcol = (bx - 10) * 128; }
    int ar = threadIdx.x >> 2;
    const float* ap[4];
    #pragma unroll
    for (int q = 0; q < 4; q++) ap[q] = h1 + (size_t)(m0 + ar + 64 * q) * DD;
    sgemm_core(ap[0], ap[1], ap[2], ap[3], B, ldb, bcol, C, ldb, bcol, DD, NT, m0);
}

// ---------------------------------------------------------------------------
// RoPE
// ---------------------------------------------------------------------------
__global__ void __launch_bounds__(512) k_rope_q() {
    int t = blockIdx.x;
    int h = threadIdx.x >> 5, i = threadIdx.x & 31;
    int pos = t & (SS - 1);
    float ang = (float)pos * g_invf[i];
    float s, c; sincosf(ang, &s, &c);
    size_t base = (size_t)t * DD + h * DH + i;
    float x1 = g_q[base], x2 = g_q[base + 32];
    g_q[base] = x1 * c - x2 * s;
    g_q[base + 32] = x2 * c + x1 * s;
}
__global__ void __launch_bounds__(128) k_rope_k() {
    int t = blockIdx.x;
    int h = threadIdx.x >> 5, i = threadIdx.x & 31;
    int pos = t & (SS - 1);
    float ang = (float)pos * g_invf[i];
    float s, c; sincosf(ang, &s, &c);
    size_t base = (size_t)t * KVD + h * DH + i;
    float x1 = g_k[base], x2 = g_k[base + 32];
    g_k[base] = x1 * c - x2 * s;
    g_k[base + 32] = x2 * c + x1 * s;
}

// ---------------------------------------------------------------------------
// Causal GQA flash attention with packed FFMA2 dot/pv loops.
// ---------------------------------------------------------------------------
__global__ void __launch_bounds__(128) k_attn() {
    int qt = blockIdx.x;
    int bh = blockIdx.y;
    int b = bh >> 4, h = bh & 15, hk = h >> 2;
    int tid = threadIdx.x;
    extern __shared__ float sm[];
    float* Ks = sm;
    float* Vs = sm + 4096;
    float* Sr = sm + 8192;

    int qi = qt * 128 + tid;
    int t  = b * SS + qi;
    float2 q2[32];
    {
        const float4* qp = (const float4*)(g_q + (size_t)t * DD + h * DH);
        #pragma unroll
        for (int u = 0; u < 16; u++) {
            float4 x = qp[u];
            q2[2 * u]     = make_float2(x.x * 0.125f, x.y * 0.125f);
            q2[2 * u + 1] = make_float2(x.z * 0.125f, x.w * 0.125f);
        }
    }
    float2 a2[32];
    #pragma unroll
    for (int d = 0; d < 32; d++) a2[d] = make_float2(0.f, 0.f);
    float m = -3e38f, l = 0.f;

    int jmax = 2 * qt + 1;
    for (int jt = 0; jt <= jmax; jt++) {
        int kb = b * SS + jt * 64;
        #pragma unroll
        for (int u = 0; u < 8; u++) {
            int lin = u * 128 + tid;
            int row = lin >> 4, c4 = lin & 15;
            *(float4*)(Ks + row * 64 + c4 * 4) =
                *(const float4*)(g_k + (size_t)(kb + row) * KVD + hk * DH + c4 * 4);
            *(float4*)(Vs + row * 64 + c4 * 4) =
                *(const float4*)(g_v + (size_t)(kb + row) * KVD + hk * DH + c4 * 4);
        }
        __syncthreads();
        int lim = qi - jt * 64;
        if (lim >= 0) {
            int cmax = lim < 63 ? lim : 63;
            float smax = -3e38f;
            for (int c = 0; c <= cmax; c++) {
                const float4* kr = (const float4*)(Ks + c * 64);
                ull s2 = 0ull;
                #pragma unroll
                for (int d4 = 0; d4 < 16; d4++) {
                    float4 kv = kr[d4];
                    fma2(s2, *(ull*)&q2[2 * d4],     *(ull*)&kv.x);
                    fma2(s2, *(ull*)&q2[2 * d4 + 1], *(ull*)&kv.z);
                }
                float2 sr = up2(s2);
                float s = sr.x + sr.y;
                Sr[tid * 65 + c] = s;
                smax = fmaxf(smax, s);
            }
            float mnew = fmaxf(m, smax);
            float corr = __expf(m - mnew);
            l *= corr;
            #pragma unroll
            for (int d = 0; d < 32; d++) { a2[d].x *= corr; a2[d].y *= corr; }
            for (int c = 0; c <= cmax; c++) {
                float p = __expf(Sr[tid * 65 + c] - mnew);
                l += p;
                ull pd = pk2(p, p);
                const float4* vr = (const float4*)(Vs + c * 64);
                #pragma unroll
                for (int d4 = 0; d4 < 16; d4++) {
                    float4 vv = vr[d4];
                    fma2(*(ull*)&a2[2 * d4],     *(ull*)&vv.x, pd);
                    fma2(*(ull*)&a2[2 * d4 + 1], *(ull*)&vv.z, pd);
                }
            }
            m = mnew;
        }
        __syncthreads();
    }
    float inv = 1.0f / l;
    float4* op = (float4*)(g_ctx + (size_t)t * DD + h * DH);
    #pragma unroll
    for (int u = 0; u < 16; u++)
        op[u] = make_float4(a2[2 * u].x * inv, a2[2 * u].y * inv,
                            a2[2 * u + 1].x * inv, a2[2 * u + 1].y * inv);
}

// ---------------------------------------------------------------------------
// residual add + clip + RMSNorm2
// ---------------------------------------------------------------------------
__global__ void __launch_bounds__(256) k_post(const float* __restrict__ hidden,
                                              const float* __restrict__ w2) {
    int t = blockIdx.x, i = threadIdx.x;
    float4 hv = ((const float4*)(hidden + (size_t)t * DD))[i];
    float4 av = ((const float4*)(g_attn + (size_t)t * DD))[i];
    float4 s;
    s.x = fminf(fmaxf(hv.x + av.x, -100.f), 100.f);
    s.y = fminf(fmaxf(hv.y + av.y, -100.f), 100.f);
    s.z = fminf(fmaxf(hv.z + av.z, -100.f), 100.f);
    s.w = fminf(fmaxf(hv.w + av.w, -100.f), 100.f);
    ((float4*)(g_res2 + (size_t)t * DD))[i] = s;
    float ss = s.x * s.x + s.y * s.y + s.z * s.z + s.w * s.w;
    __shared__ float red[8];
    int lane = i & 31, wp = i >> 5;
    #pragma unroll
    for (int o = 16; o; o >>= 1) ss += __shfl_xor_sync(0xffffffffu, ss, o);
    if (!lane) red[wp] = ss;
    __syncthreads();
    if (i == 0) { float z = 0.f; for (int j = 0; j < 8; j++) z += red[j]; red[0] = z; }
    __syncthreads();
    float rs = rsqrtf(red[0] * (1.0f / DD) + EPS_RMS);
    float4 wv = ((const float4*)w2)[i];
    ((float4*)(g_flat + (size_t)t * DD))[i] =
        make_float4(s.x * rs * wv.x, s.y * rs * wv.y, s.z * rs * wv.z, s.w * rs * wv.w);
}

// ---------------------------------------------------------------------------
// Router
// ---------------------------------------------------------------------------
__global__ void __launch_bounds__(256) k_router(const float* __restrict__ Wr) {
    int t = blockIdx.x;
    int lane = threadIdx.x & 31, w = threadIdx.x >> 5;
    const float* fr = g_flat + (size_t)t * DD;
    float s = 0.f;
    for (int d = lane; d < DD; d += 32) s += fr[d] * Wr[d * NEXP + w];
    #pragma unroll
    for (int o = 16; o; o >>= 1) s += __shfl_xor_sync(0xffffffffu, s, o);
    __shared__ float lg[NEXP];
    if (!lane) lg[w] = s;
    __syncthreads();
    if (threadIdx.x == 0) {
        float l0 = -3e38f; int i0 = 0;
        #pragma unroll
        for (int e2 = 0; e2 < NEXP; e2++) if (lg[e2] > l0) { l0 = lg[e2]; i0 = e2; }
        float l1 = -3e38f; int i1 = 0;
        #pragma unroll
        for (int e2 = 0; e2 < NEXP; e2++)
            if (e2 != i0 && lg[e2] > l1) { l1 = lg[e2]; i1 = e2; }
        float p1 = __expf(l1 - l0);
        float w0 = 1.0f / (1.0f + p1), w1 = p1 / (1.0f + p1);
        int pos0 = atomicAdd(&g_cnt[i0], 1);
        g_list[i0 * NT + pos0] = t;
        g_tok_e[t * 2] = i0; g_tok_i[t * 2] = pos0; g_tok_w[t * 2] = w0;
        int pos1 = atomicAdd(&g_cnt[i1], 1);
        g_list[i1 * NT + pos1] = t;
        g_tok_e[t * 2 + 1] = i1; g_tok_i[t * 2 + 1] = pos1; g_tok_w[t * 2 + 1] = w1;
    }
}

// ---------------------------------------------------------------------------
// SiLU(g)*u in place into g_G
// ---------------------------------------------------------------------------
__global__ void __launch_bounds__(256) k_act() {
    int e = blockIdx.y, r = blockIdx.x;
    if (r >= g_cnt[e]) return;
    size_t base4 = (((size_t)e * NT + r) * FF) >> 2;
    float4* G4 = (float4*)g_G;
    const float4* U4 = (const float4*)g_U;
    for (int f = threadIdx.x; f < FF / 4; f += 256) {
        float4 g = G4[base4 + f], u = U4[base4 + f];
        g.x = g.x / (1.f + __expf(-g.x)) * u.x;
        g.y = g.y / (1.f + __expf(-g.y)) * u.y;
        g.z = g.z / (1.f + __expf(-g.z)) * u.z;
        g.w = g.w / (1.f + __expf(-g.w)) * u.w;
        G4[base4 + f] = g;
    }
}

// ---------------------------------------------------------------------------
// Final combine
// ---------------------------------------------------------------------------
__global__ void __launch_bounds__(256) k_combine(float* __restrict__ out) {
    int t = blockIdx.x, i = threadIdx.x;
    int e0 = g_tok_e[t * 2],     i0 = g_tok_i[t * 2];     float w0 = g_tok_w[t * 2];
    int e1 = g_tok_e[t * 2 + 1], i1 = g_tok_i[t * 2 + 1]; float w1 = g_tok_w[t * 2 + 1];
    const float4* o0 = (const float4*)(g_O + ((size_t)e0 * NT + i0) * DD);
    const float4* o1 = (const float4*)(g_O + ((size_t)e1 * NT + i1) * DD);
    const float4* rr = (const float4*)(g_res2 + (size_t)t * DD);
    float4 a = rr[i], x = o0[i], y = o1[i], o;
    o.x = fminf(fmaxf(a.x + w0 * x.x + w1 * y.x, -100.f), 100.f);
    o.y = fminf(fmaxf(a.y + w0 * x.y + w1 * y.y, -100.f), 100.f);
    o.z = fminf(fmaxf(a.z + w0 * x.z + w1 * y.z, -100.f), 100.f);
    o.w = fminf(fmaxf(a.w + w0 * x.w + w1 * y.w, -100.f), 100.f);
    ((float4*)(out + (size_t)t * DD))[i] = o;
}

// ---------------------------------------------------------------------------
// Host launcher
// ---------------------------------------------------------------------------
extern "C" void kernel_launch(void* const* d_in, const int* in_sizes, int n_in,
                              void* d_out, int out_size) {
    const float* hidden = (const float*)d_in[0];
    const float* ln1    = (const float*)d_in[1];
    const float* ln2    = (const float*)d_in[2];
    const float* Wq     = (const float*)d_in[3];
    const float* Wk     = (const float*)d_in[4];
    const float* Wv     = (const float*)d_in[5];
    const float* Wo     = (const float*)d_in[6];
    const float* Wr     = (const float*)d_in[7];
    const float* Wg     = (const float*)d_in[8];
    const float* Wu     = (const float*)d_in[9];
    const float* Wd     = (const float*)d_in[10];
    float* out = (float*)d_out;
    (void)in_sizes; (void)n_in; (void)out_size;

    float *p_h1, *p_ctx, *p_attn, *p_flat, *p_G, *p_U, *p_O;
    int *p_lst, *p_cnt;
    cudaGetSymbolAddress((void**)&p_h1,  g_h1);
    cudaGetSymbolAddress((void**)&p_ctx, g_ctx);
    cudaGetSymbolAddress((void**)&p_attn,g_attn);
    cudaGetSymbolAddress((void**)&p_flat,g_flat);
    cudaGetSymbolAddress((void**)&p_G,   g_G);
    cudaGetSymbolAddress((void**)&p_U,   g_U);
    cudaGetSymbolAddress((void**)&p_O,   g_O);
    cudaGetSymbolAddress((void**)&p_lst, g_list);
    cudaGetSymbolAddress((void**)&p_cnt, g_cnt);

    const int ATTN_SMEM = (4096 + 4096 + 128 * 65) * 4;   // 66048 B
    static int s_attr_done = 0;
    if (!s_attr_done) {
        cudaFuncSetAttribute(k_attn, cudaFuncAttributeMaxDynamicSharedMemorySize, ATTN_SMEM);
        s_attr_done = 1;
    }

    k_zero_init<<<1, 32>>>();
    k_rms1<<<NT, 256>>>(hidden, ln1);

    // Fused QKV projection (cols 0..1023 -> Wq, 1024..1279 -> Wk, 1280..1535 -> Wv)
    k_sgemm_qkv<<<dim3(12, NT / BM), 256>>>(p_h1, Wq, Wk, Wv);

    k_rope_q<<<NT, 512>>>();
    k_rope_k<<<NT, 128>>>();

    k_attn<<<dim3(16, 32), 128, ATTN_SMEM>>>();

    // Wo projection
    k_sgemm<<<dim3(8, NT / BM, 1), 256>>>((const float*)p_ctx, Wo, p_attn,
                                          NT, 1024, 1024, 0, 0, 0, 0, 0);

    k_post<<<NT, 256>>>(hidden, ln2);
    k_router<<<NT, 256>>>(Wr);

    // Expert FFN
    k_sgemm<<<dim3(16, NT / BM, NEXP), 256>>>((const float*)p_flat, Wg, p_G, 0, FF, DD,
                                              p_lst, p_cnt, 0, (size_t)DD * FF, (size_t)NT * FF);
    k_sgemm<<<dim3(16, NT / BM, NEXP), 256>>>((const float*)p_flat, Wu, p_U, 0, FF, DD,
                                              p_lst, p_cnt, 0, (size_t)DD * FF, (size_t)NT * FF);
    k_act<<<dim3(NT, NEXP), 256>>>();
    k_sgemm<<<dim3(8, NT / BM, NEXP), 256>>>((const float*)p_G, Wd, p_O, 0, DD, FF,
                                             0, p_cnt, (size_t)NT * FF, (size_t)FF * DD, (size_t)NT * DD);

    k_combine<<<NT, 256>>>(out);
}